// round 15
// baseline (speedup 1.0000x reference)
#include <cuda_runtime.h>
#include <cuda_fp16.h>
#include <math.h>
#include <stdint.h>

// Problem constants
#define Bn 4
#define Sn 2048
#define Hn 512
#define NHn 8
#define DHn 64
#define Fn 2048
#define Ln 4
#define Mn (Bn * Sn)  // 8192
#define QKVS 1536
#define L2E 1.4426950408889634f

// ---------------- scratch (device globals; no allocation allowed) ----------
__device__ float g_x[Mn * Hn];
__device__ float g_attn[Mn * Hn];
__device__ __half g_sinv[(size_t)Bn * Sn * Sn];   // inv-scale * L2E (fp16)
__device__ float g_msk2[Bn * Sn];                 // mask * L2E

__device__ __half g_qkv[(size_t)Mn * QKVS];
__device__ __half g_ch[Mn * Hn];   // ctx
__device__ __half g_xh[Mn * Hn];
__device__ __half g_th[Mn * Hn];   // attn (post ln1)
__device__ __half g_fh[(size_t)Mn * Fn];

// weights (single fp16)
__device__ __half g_wqkv[Ln * Hn * QKVS];
__device__ __half g_wo[Ln * Hn * Hn];
__device__ __half g_wi[Ln * Hn * Fn];
__device__ __half g_w2[Ln * Fn * Hn];
__device__ float g_bqkv[Ln * QKVS];
__device__ __half g_pbb[(size_t)NHn * Sn * Sn];   // fp16 position bias * L2E

// ---------------- helpers ---------------------------------------------------
__device__ __forceinline__ uint32_t cvta_smem(const void* p) {
    uint32_t a;
    asm("{ .reg .u64 t; cvta.to.shared.u64 t, %1; cvt.u32.u64 %0, t; }"
        : "=r"(a) : "l"(p));
    return a;
}

#define CP16(dst, src) \
    asm volatile("cp.async.cg.shared.global [%0], [%1], 16;" :: "r"(dst), "l"(src))
#define CP_COMMIT() asm volatile("cp.async.commit_group;" ::: "memory")
#define CP_WAIT0()  asm volatile("cp.async.wait_group 0;" ::: "memory")
#define CP_WAIT2()  asm volatile("cp.async.wait_group 2;" ::: "memory")

#define LDSM4(r, addr)                                                          \
    asm volatile("ldmatrix.sync.aligned.m8n8.x4.shared.b16 {%0,%1,%2,%3}, [%4];"\
        : "=r"((r)[0]), "=r"((r)[1]), "=r"((r)[2]), "=r"((r)[3]) : "r"(addr))
#define LDSM4T(r01, r23, addr)                                                  \
    asm volatile("ldmatrix.sync.aligned.m8n8.x4.trans.shared.b16 {%0,%1,%2,%3}, [%4];"\
        : "=r"((r01)[0]), "=r"((r01)[1]), "=r"((r23)[0]), "=r"((r23)[1]) : "r"(addr))

__device__ __forceinline__ void mma16816(float* c, const uint32_t* a, const uint32_t* b) {
    asm volatile(
        "mma.sync.aligned.m16n8k16.row.col.f32.f16.f16.f32 "
        "{%0,%1,%2,%3}, {%4,%5,%6,%7}, {%8,%9}, {%0,%1,%2,%3};"
        : "+f"(c[0]), "+f"(c[1]), "+f"(c[2]), "+f"(c[3])
        : "r"(a[0]), "r"(a[1]), "r"(a[2]), "r"(a[3]), "r"(b[0]), "r"(b[1]));
}

__device__ __forceinline__ uint32_t pack_h2(float lo, float hi) {
    __half2 p = __floats2half2_rn(lo, hi);
    return *reinterpret_cast<uint32_t*>(&p);
}
__device__ __forceinline__ float h_lo(uint32_t u) {
    return __half2float(__ushort_as_half((unsigned short)(u & 0xffffu)));
}
__device__ __forceinline__ float h_hi(uint32_t u) {
    return __half2float(__ushort_as_half((unsigned short)(u >> 16)));
}
__device__ __forceinline__ float ex2f(float x) {
    float y;
    asm("ex2.approx.ftz.f32 %0, %1;" : "=f"(y) : "f"(x));
    return y;
}
__device__ __forceinline__ float rcpf(float x) {
    float y;
    asm("rcp.approx.ftz.f32 %0, %1;" : "=f"(y) : "f"(x));
    return y;
}
// 1/scale = (u + 60000) / (9u + 480000), u = max(dt_ms, 0)
__device__ __forceinline__ float sinv_of(int dt) {
    float u = fmaxf((float)dt, 0.0f);
    return (u + 60000.0f) * rcpf(fmaf(u, 9.0f, 480000.0f));
}

// convert 8 fp32 -> fp16x8 (scaled) and store
__device__ __forceinline__ void cvt8_store_s(
    const float* __restrict__ src, __half* __restrict__ h, float sc)
{
    float4 a = *(const float4*)src;
    float4 b = *(const float4*)(src + 4);
    float v[8] = {a.x, a.y, a.z, a.w, b.x, b.y, b.z, b.w};
    __align__(16) __half hh[8];
#pragma unroll
    for (int j = 0; j < 8; j++) hh[j] = __float2half_rn(v[j] * sc);
    *(uint4*)h = *(const uint4*)hh;
}
__device__ __forceinline__ void cvt8_store(
    const float* __restrict__ src, __half* __restrict__ h)
{
    cvt8_store_s(src, h, 1.0f);
}

// smem stage layout for dense GEMM (BK=32): A 128x80B, B 32x272B
#define OFF_AH 0
#define OFF_BH 10240
#define STAGE_BYTES 18944   // x2 stages = 37888

// ---------------------------------------------------------------------------
// sinv[b][q][k] = (1/scale)*L2E (fp16), plus mask*L2E (blocks 0..31).
// ---------------------------------------------------------------------------
__global__ void __launch_bounds__(256) sinv_kernel(
    const int* __restrict__ ts, __half* __restrict__ sv,
    const float* __restrict__ mask, float* __restrict__ msk2)
{
    const int bq = blockIdx.x;
    if (bq < 32) {
        int i = bq * 256 + threadIdx.x;
        msk2[i] = mask[i] * L2E;
    }
    const int b = bq >> 11;
    const int tq = ts[bq];
    const int* tr = ts + b * Sn;
    __half* out = sv + (size_t)bq * Sn;
#pragma unroll
    for (int kk = 0; kk < 2; kk++) {
        int k = (threadIdx.x + (kk << 8)) << 2;
        int4 tk = *(const int4*)(tr + k);
        uint2 o;
        o.x = pack_h2(sinv_of(tq - tk.x) * L2E, sinv_of(tq - tk.y) * L2E);
        o.y = pack_h2(sinv_of(tq - tk.z) * L2E, sinv_of(tq - tk.w) * L2E);
        *(uint2*)(out + k) = o;
    }
}

// ---------------------------------------------------------------------------
// Mega prep: weight cvt + qkv pack + bias pack + pb cvt(*L2E) + x cvt
// ---------------------------------------------------------------------------
__global__ void __launch_bounds__(256) prep_kernel(
    const float* __restrict__ wq, const float* __restrict__ wk,
    const float* __restrict__ wv, const float* __restrict__ wo,
    const float* __restrict__ wi, const float* __restrict__ wo2,
    const float* __restrict__ bq, const float* __restrict__ bk,
    const float* __restrict__ bv, const float* __restrict__ pb,
    const float* __restrict__ qs,
    __half* __restrict__ wqkv, __half* __restrict__ woh,
    __half* __restrict__ wih, __half* __restrict__ w2h,
    float* __restrict__ bqkv, __half* __restrict__ pbb,
    __half* __restrict__ xh)
{
    const int blk = blockIdx.x;
    if (blk < 1536) {
        const int seg = blk >> 9, b2 = blk & 511;
        const float* src = (seg == 0) ? wq : (seg == 1) ? wk : wv;
        const int coloff = seg << 9;
        const int i = (b2 * 256 + threadIdx.x) * 8;
        const int row = i >> 9, col = i & 511;
        cvt8_store(src + i, wqkv + (size_t)row * QKVS + coloff + col);
    } else if (blk < 2048) {
        const int i = ((blk - 1536) * 256 + threadIdx.x) * 8;
        cvt8_store(wo + i, woh + i);
    } else if (blk < 4096) {
        const int i = ((blk - 2048) * 256 + threadIdx.x) * 8;
        cvt8_store(wi + i, wih + i);
    } else if (blk < 6144) {
        const int i = ((blk - 4096) * 256 + threadIdx.x) * 8;
        cvt8_store(wo2 + i, w2h + i);
    } else if (blk < 6147) {
        const int i0 = ((blk - 6144) * 256 + threadIdx.x) * 8;
#pragma unroll
        for (int j = 0; j < 8; j++) {
            const int idx = i0 + j;
            const int l = idx / QKVS, jj = idx % QKVS;
            const int seg = jj >> 9, col = jj & 511;
            const float* s = (seg == 0) ? bq : (seg == 1) ? bk : bv;
            bqkv[idx] = s[l * Hn + col];
        }
    } else if (blk < 22531) {
        const size_t i = ((size_t)(blk - 6147) * 256 + threadIdx.x) * 8;
        cvt8_store_s(pb + i, pbb + i, L2E);
    } else {
        const int i = ((blk - 22531) * 256 + threadIdx.x) * 8;
        cvt8_store(qs + i, xh + i);
    }
}

// ---------------------------------------------------------------------------
// HMMA GEMM, single fp16, 1-pass: C = Ah*Wh.  CTA 128x128, BK=32, 8 warps.
// (R13 known-good version)
// ---------------------------------------------------------------------------
template <int EPI>
__global__ void __launch_bounds__(256, 2) hmma_gemm(
    const __half* __restrict__ Ahp, const __half* __restrict__ Bhp,
    const float* __restrict__ bias, const float* __restrict__ res,
    float* __restrict__ C, __half* __restrict__ Cho, int K, int N)
{
    extern __shared__ char smem[];
    const uint32_t sb = cvta_smem(smem);
    const int tid = threadIdx.x, lane = tid & 31, warp = tid >> 5;
    const int m0 = blockIdx.y << 7, n0 = blockIdx.x << 7;
    const int wm0 = (warp >> 2) << 6, wn0 = (warp & 3) << 5;

    const int ar = tid >> 2, ac = tid & 3;
    const int br = tid >> 4, bc = tid & 15;

    auto load_stage = [&](int st, int kc) {
        const int k0 = kc << 5;
        const uint32_t s = sb + st * STAGE_BYTES;
        const size_t aoff0 = (size_t)(m0 + ar) * K + k0 + ac * 8;
        const size_t aoff1 = (size_t)(m0 + ar + 64) * K + k0 + ac * 8;
        CP16(s + OFF_AH + ar * 80 + ac * 16, Ahp + aoff0);
        CP16(s + OFF_AH + (ar + 64) * 80 + ac * 16, Ahp + aoff1);
        const size_t boff0 = (size_t)(k0 + br) * N + n0 + bc * 8;
        const size_t boff1 = (size_t)(k0 + br + 16) * N + n0 + bc * 8;
        CP16(s + OFF_BH + br * 272 + bc * 16, Bhp + boff0);
        CP16(s + OFF_BH + (br + 16) * 272 + bc * 16, Bhp + boff1);
        CP_COMMIT();
    };

    float acc[4][4][4];
#pragma unroll
    for (int i = 0; i < 4; i++)
#pragma unroll
        for (int j = 0; j < 4; j++)
#pragma unroll
            for (int r = 0; r < 4; r++) acc[i][j][r] = 0.0f;

    const int nch = K >> 5;
    load_stage(0, 0);

    for (int kc = 0; kc < nch; kc++) {
        const int cur = kc & 1;
        CP_WAIT0();
        __syncthreads();
        if (kc + 1 < nch) load_stage(cur ^ 1, kc + 1);

        const uint32_t s = sb + cur * STAGE_BYTES;
#pragma unroll
        for (int ks = 0; ks < 2; ks++) {
            const uint32_t aoff =
                (wm0 + (lane & 15)) * 80 + ((ks << 4) + ((lane >> 4) << 3)) * 2;
            const uint32_t boff =
                ((ks << 4) + (lane & 15)) * 272 + (wn0 + ((lane >> 4) << 3)) * 2;

            uint32_t ah[4][4];
#pragma unroll
            for (int mt = 0; mt < 4; mt++)
                LDSM4(ah[mt], s + OFF_AH + aoff + mt * (16 * 80));
            uint32_t b[4][2];
            LDSM4T(b[0], b[1], s + OFF_BH + boff);
            LDSM4T(b[2], b[3], s + OFF_BH + boff + 32);
#pragma unroll
            for (int mt = 0; mt < 4; mt++)
#pragma unroll
                for (int nt = 0; nt < 4; nt++) mma16816(acc[mt][nt], ah[mt], b[nt]);
        }
    }

#pragma unroll
    for (int mt = 0; mt < 4; mt++) {
        const int m = m0 + wm0 + mt * 16 + (lane >> 2);
#pragma unroll
        for (int nt = 0; nt < 4; nt++) {
            const int n = n0 + wn0 + nt * 8 + (lane & 3) * 2;
            float2 bv = *(const float2*)(bias + n);
            float o0 = acc[mt][nt][0] + bv.x;
            float o1 = acc[mt][nt][1] + bv.y;
            float o2 = acc[mt][nt][2] + bv.x;
            float o3 = acc[mt][nt][3] + bv.y;
            if (EPI == 1) {
                float2 r0 = *(const float2*)(res + (size_t)m * N + n);
                float2 r1 = *(const float2*)(res + (size_t)(m + 8) * N + n);
                o0 += r0.x; o1 += r0.y; o2 += r1.x; o3 += r1.y;
                *(float2*)(C + (size_t)m * N + n) = make_float2(o0, o1);
                *(float2*)(C + (size_t)(m + 8) * N + n) = make_float2(o2, o3);
            } else {
                if (EPI == 2) {
                    o0 = 0.5f * o0 * (1.0f + erff(o0 * 0.7071067811865475f));
                    o1 = 0.5f * o1 * (1.0f + erff(o1 * 0.7071067811865475f));
                    o2 = 0.5f * o2 * (1.0f + erff(o2 * 0.7071067811865475f));
                    o3 = 0.5f * o3 * (1.0f + erff(o3 * 0.7071067811865475f));
                }
                *(uint32_t*)(Cho + (size_t)m * N + n) = pack_h2(o0, o1);
                *(uint32_t*)(Cho + (size_t)(m + 8) * N + n) = pack_h2(o2, o3);
            }
        }
    }
}

// ---------------------------------------------------------------------------
// Flash attention, fp16 1-pass, log2-domain, f32 ex2, branch-free.
// 3-stage KV cp.async pipeline (always-commit). Hot loop body unchanged.
// smem: Q 18432; 3 KV stages of 18432 (K 9216, V 9216) = 73728.
// ---------------------------------------------------------------------------
#define FSTG 18432
__global__ void __launch_bounds__(256, 2) flash_kernel(
    const __half* __restrict__ QKV,
    const __half* __restrict__ sinv, const __half* __restrict__ pbb,
    const float* __restrict__ msk2, __half* __restrict__ Ch)
{
    extern __shared__ char smem[];
    const uint32_t sb = cvta_smem(smem);
    const int tid = threadIdx.x, lane = tid & 31, warp = tid >> 5;
    const int qb = blockIdx.x << 7;
    const int bh = blockIdx.y, b = bh & 3, h = bh >> 2;
    const uint32_t sQ = sb;
    const uint32_t sKV = sb + 18432;

    const int kvr = tid >> 3, kvc = tid & 7;
    auto load_kv = [&](int st, int kt) {
        const uint32_t s = sKV + st * FSTG;
        const int k0n = kt << 6;
#pragma unroll
        for (int i = 0; i < 2; i++) {
            int r = kvr + (i << 5);
            size_t off = ((size_t)(b * Sn + k0n + r)) * QKVS + h * 64 + kvc * 8;
            uint32_t d = s + r * 144 + kvc * 16;
            CP16(d, QKV + off + 512);           // K
            CP16(d + 9216, QKV + off + 1024);   // V
        }
    };

    // Q + stage 0 (group 0), stage 1 (group 1)
#pragma unroll
    for (int i = 0; i < 4; i++) {
        int idx = tid + (i << 8);
        int r = idx >> 3, c = idx & 7;
        size_t off = ((size_t)(b * Sn + qb + r)) * QKVS + h * 64 + c * 8;
        CP16(sQ + r * 144 + c * 16, QKV + off);
    }
    load_kv(0, 0);
    CP_COMMIT();
    load_kv(1, 1);
    CP_COMMIT();

    const int qr0 = qb + (warp << 4) + (lane >> 2);
    const __half* sv0 = sinv + ((size_t)(b * Sn + qr0)) * Sn;
    const __half* sv1 = sv0 + (size_t)8 * Sn;
    const __half* pb0 = pbb + ((size_t)(h * Sn + qr0)) * Sn;
    const __half* pb1 = pb0 + (size_t)8 * Sn;
    const float* mrow = msk2 + b * Sn;

    float oacc[8][4];
#pragma unroll
    for (int t = 0; t < 8; t++)
#pragma unroll
        for (int r = 0; r < 4; r++) oacc[t][r] = 0.0f;
    float m0 = -1e30f, m1 = -1e30f, l0 = 0.0f, l1 = 0.0f;

    int cur = 0, nxt = 2;
    for (int it = 0; it < 32; it++) {
        if (it + 2 < 32) load_kv(nxt, it + 2);
        CP_COMMIT();
        CP_WAIT2();
        __syncthreads();

        const uint32_t stg = sKV + cur * FSTG;
        float sacc[8][4];
#pragma unroll
        for (int t = 0; t < 8; t++)
#pragma unroll
            for (int r = 0; r < 4; r++) sacc[t][r] = 0.0f;

        // S = Qh * Kh
#pragma unroll
        for (int kc = 0; kc < 4; kc++) {
            uint32_t aq[4];
            const uint32_t qa = sQ + ((warp << 4) + (lane & 15)) * 144 +
                                ((kc << 4) + ((lane >> 4) << 3)) * 2;
            LDSM4(aq, qa);
#pragma unroll
            for (int nb = 0; nb < 4; nb++) {
                uint32_t kb[4];
                const uint32_t ka = stg + ((nb << 4) + (lane & 15)) * 144 +
                                    ((kc << 4) + ((lane >> 4) << 3)) * 2;
                LDSM4(kb, ka);
#pragma unroll
                for (int tt = 0; tt < 2; tt++) {
                    const int t = (nb << 1) + tt;
                    uint32_t b_[2] = {kb[tt], kb[tt + 2]};
                    mma16816(sacc[t], aq, b_);
                }
            }
        }

        // scoring (log2 domain): s = qk*sinv2 + pb2 + mk2, online softmax
        const int k0 = it << 6;
        float tm0 = -1e30f, tm1 = -1e30f;
#pragma unroll
        for (int t = 0; t < 8; t++) {
            const int n = k0 + (t << 3) + ((lane & 3) << 1);
            uint32_t su0 = *(const uint32_t*)(sv0 + n);
            uint32_t su1 = *(const uint32_t*)(sv1 + n);
            float2 mk = *(const float2*)(mrow + n);
            uint32_t pu0 = *(const uint32_t*)(pb0 + n);
            uint32_t pu1 = *(const uint32_t*)(pb1 + n);
            sacc[t][0] = fmaf(sacc[t][0], h_lo(su0), h_lo(pu0) + mk.x);
            sacc[t][1] = fmaf(sacc[t][1], h_hi(su0), h_hi(pu0) + mk.y);
            sacc[t][2] = fmaf(sacc[t][2], h_lo(su1), h_lo(pu1) + mk.x);
            sacc[t][3] = fmaf(sacc[t][3], h_hi(su1), h_hi(pu1) + mk.y);
            tm0 = fmaxf(tm0, fmaxf(sacc[t][0], sacc[t][1]));
            tm1 = fmaxf(tm1, fmaxf(sacc[t][2], sacc[t][3]));
        }
        tm0 = fmaxf(tm0, __shfl_xor_sync(0xffffffffu, tm0, 1));
        tm0 = fmaxf(tm0, __shfl_xor_sync(0xffffffffu, tm0, 2));
        tm1 = fmaxf(tm1, __shfl_xor_sync(0xffffffffu, tm1, 1));
        tm1 = fmaxf(tm1, __shfl_xor_sync(0xffffffffu, tm1, 2));
        const float mn0 = fmaxf(m0, tm0), mn1 = fmaxf(m1, tm1);
        const float c0 = ex2f(m0 - mn0), c1 = ex2f(m1 - mn1);
        m0 = mn0; m1 = mn1;

        float rs0 = 0.0f, rs1 = 0.0f;
        uint32_t ap[4][4];
#pragma unroll
        for (int t = 0; t < 8; t++) {
            float p00 = ex2f(sacc[t][0] - m0);
            float p01 = ex2f(sacc[t][1] - m0);
            float p10 = ex2f(sacc[t][2] - m1);
            float p11 = ex2f(sacc[t][3] - m1);
            rs0 += p00 + p01; rs1 += p10 + p11;
            const int kc2 = t >> 1, hf = (t & 1) << 1;
            ap[kc2][hf] = pack_h2(p00, p01);
            ap[kc2][hf + 1] = pack_h2(p10, p11);
        }
        rs0 += __shfl_xor_sync(0xffffffffu, rs0, 1);
        rs0 += __shfl_xor_sync(0xffffffffu, rs0, 2);
        rs1 += __shfl_xor_sync(0xffffffffu, rs1, 1);
        rs1 += __shfl_xor_sync(0xffffffffu, rs1, 2);
        l0 = l0 * c0 + rs0;
        l1 = l1 * c1 + rs1;
#pragma unroll
        for (int t = 0; t < 8; t++) {
            oacc[t][0] *= c0; oacc[t][1] *= c0;
            oacc[t][2] *= c1; oacc[t][3] *= c1;
        }

        // O += Ph * Vh
#pragma unroll
        for (int kc2 = 0; kc2 < 4; kc2++) {
#pragma unroll
            for (int dnb = 0; dnb < 4; dnb++) {
                uint32_t vf[2][2];
                const uint32_t va = stg + 9216 +
                    ((kc2 << 4) + (lane & 15)) * 144 +
                    ((dnb << 4) + ((lane >> 4) << 3)) * 2;
                LDSM4T(vf[0], vf[1], va);
#pragma unroll
                for (int tt = 0; tt < 2; tt++)
                    mma16816(oacc[(dnb << 1) + tt], ap[kc2], vf[tt]);
            }
        }
        __syncthreads();
        cur = (cur == 2) ? 0 : cur + 1;
        nxt = (nxt == 2) ? 0 : nxt + 1;
    }

    const float inv0 = 1.0f / l0, inv1 = 1.0f / l1;
#pragma unroll
    for (int t = 0; t < 8; t++) {
        const int d = (t << 3) + ((lane & 3) << 1);
        const size_t o0 = ((size_t)(b * Sn + qr0)) * Hn + h * 64 + d;
        const size_t o1 = ((size_t)(b * Sn + qr0 + 8)) * Hn + h * 64 + d;
        *(uint32_t*)(Ch + o0) = pack_h2(oacc[t][0] * inv0, oacc[t][1] * inv0);
        *(uint32_t*)(Ch + o1) = pack_h2(oacc[t][2] * inv1, oacc[t][3] * inv1);
    }
}

// ---------------------------------------------------------------------------
// LayerNorm over H=512; optional fp16 output.
// ---------------------------------------------------------------------------
__global__ void __launch_bounds__(256) ln_kernel(
    const float* __restrict__ in, const float* __restrict__ g,
    const float* __restrict__ bta, float* __restrict__ out,
    __half* __restrict__ ho)
{
    const size_t base = (size_t)blockIdx.x * Hn;
    const int tid = threadIdx.x;
    __shared__ float sh[8], sh2[8];
    float x0 = in[base + tid], x1 = in[base + tid + 256];
    float s = x0 + x1;
    for (int o = 16; o; o >>= 1) s += __shfl_xor_sync(0xffffffffu, s, o);
    if ((tid & 31) == 0) sh[tid >> 5] = s;
    __syncthreads();
    s = 0.0f;
#pragma unroll
    for (int i = 0; i < 8; i++) s += sh[i];
    const float mean = s * (1.0f / Hn);
    const float d0 = x0 - mean, d1 = x1 - mean;
    float vv = d0 * d0 + d1 * d1;
    for (int o = 16; o; o >>= 1) vv += __shfl_xor_sync(0xffffffffu, vv, o);
    if ((tid & 31) == 0) sh2[tid >> 5] = vv;
    __syncthreads();
    vv = 0.0f;
#pragma unroll
    for (int i = 0; i < 8; i++) vv += sh2[i];
    const float inv = rsqrtf(vv * (1.0f / Hn) + 1e-12f);
    const float y0 = d0 * inv * g[tid] + bta[tid];
    const float y1 = d1 * inv * g[tid + 256] + bta[tid + 256];
    out[base + tid] = y0;
    out[base + tid + 256] = y1;
    if (ho) {
        ho[base + tid] = __float2half_rn(y0);
        ho[base + tid + 256] = __float2half_rn(y1);
    }
}

// ---------------------------------------------------------------------------
extern "C" void kernel_launch(void* const* d_in, const int* in_sizes, int n_in,
                              void* d_out, int out_size)
{
    (void)in_sizes; (void)n_in; (void)out_size;
    const float* qs   = (const float*)d_in[0];
    const float* mask = (const float*)d_in[1];
    const float* pb   = (const float*)d_in[2];
    const int*   ts   = (const int*)d_in[3];
    const float* wq  = (const float*)d_in[4];  const float* bq  = (const float*)d_in[5];
    const float* wk  = (const float*)d_in[6];  const float* bk  = (const float*)d_in[7];
    const float* wv  = (const float*)d_in[8];  const float* bv  = (const float*)d_in[9];
    const float* wo  = (const float*)d_in[10]; const float* bo  = (const float*)d_in[11];
    const float* l1g = (const float*)d_in[12]; const float* l1b = (const float*)d_in[13];
    const float* wi  = (const float*)d_in[14]; const float* bi  = (const float*)d_in[15];
    const float* wo2 = (const float*)d_in[16]; const float* bo2 = (const float*)d_in[17];
    const float* l2g = (const float*)d_in[18]; const float* l2b = (const float*)d_in[19];

    float *x, *attn, *bqkv, *msk2;
    cudaGetSymbolAddress((void**)&x,    g_x);
    cudaGetSymbolAddress((void**)&attn, g_attn);
    cudaGetSymbolAddress((void**)&bqkv, g_bqkv);
    cudaGetSymbolAddress((void**)&msk2, g_msk2);

    __half *qkv, *ch, *xh, *th, *fh, *pbb, *sinvp;
    cudaGetSymbolAddress((void**)&qkv, g_qkv);
    cudaGetSymbolAddress((void**)&ch, g_ch);
    cudaGetSymbolAddress((void**)&xh, g_xh);
    cudaGetSymbolAddress((void**)&th, g_th);
    cudaGetSymbolAddress((void**)&fh, g_fh);
    cudaGetSymbolAddress((void**)&pbb, g_pbb);
    cudaGetSymbolAddress((void**)&sinvp, g_sinv);

    __half *wqkvp, *wop, *wip, *w2p;
    cudaGetSymbolAddress((void**)&wqkvp, g_wqkv);
    cudaGetSymbolAddress((void**)&wop, g_wo);
    cudaGetSymbolAddress((void**)&wip, g_wi);
    cudaGetSymbolAddress((void**)&w2p, g_w2);

    const int HM_SMEM = 2 * STAGE_BYTES;  // 37888
    const int FL_SMEM = 18432 + 3 * FSTG; // 73728
    cudaFuncSetAttribute(hmma_gemm<0>, cudaFuncAttributeMaxDynamicSharedMemorySize, HM_SMEM);
    cudaFuncSetAttribute(hmma_gemm<1>, cudaFuncAttributeMaxDynamicSharedMemorySize, HM_SMEM);
    cudaFuncSetAttribute(hmma_gemm<2>, cudaFuncAttributeMaxDynamicSharedMemorySize, HM_SMEM);
    cudaFuncSetAttribute(flash_kernel, cudaFuncAttributeMaxDynamicSharedMemorySize, FL_SMEM);

    // Launch order: prep(0), sinv(1), qkv(2), flash(3) for ncu -s 5 -c 1.
    prep_kernel<<<24579, 256>>>(wq, wk, wv, wo, wi, wo2, bq, bk, bv, pb, qs,
                                wqkvp, wop, wip, w2p, bqkv, pbb, xh);
    sinv_kernel<<<Bn * Sn, 256>>>(ts, sinvp, mask, msk2);

    dim3 gqkv(QKVS / 128, Mn / 128);  // (12, 64)
    dim3 gproj(Hn / 128, Mn / 128);   // (4, 64)
    dim3 gff(Fn / 128, Mn / 128);     // (16, 64)
    dim3 gfl(Sn / 128, Bn * NHn);     // (16, 32)

    for (int l = 0; l < Ln; l++) {
        const size_t wOff  = (size_t)l * Hn * Hn;
        const size_t bOff  = (size_t)l * Hn;
        const size_t wiOff = (size_t)l * Hn * Fn;
        const size_t biOff = (size_t)l * Fn;
        const float* xres = (l == 0) ? qs : x;

        hmma_gemm<0><<<gqkv, 256, HM_SMEM>>>(xh,
            wqkvp + (size_t)l * Hn * QKVS, bqkv + l * QKVS,
            nullptr, nullptr, qkv, Hn, QKVS);

        flash_kernel<<<gfl, 256, FL_SMEM>>>(qkv, sinvp, pbb, msk2, ch);

        hmma_gemm<1><<<gproj, 256, HM_SMEM>>>(ch, wop + wOff, bo + bOff,
                                              xres, attn, nullptr, Hn, Hn);
        ln_kernel<<<Mn, 256>>>(attn, l1g + bOff, l1b + bOff, attn, th);

        hmma_gemm<2><<<gff, 256, HM_SMEM>>>(th, wip + wiOff, bi + biOff,
                                            nullptr, nullptr, fh, Hn, Fn);
        hmma_gemm<1><<<gproj, 256, HM_SMEM>>>(fh, w2p + wiOff, bo2 + bOff,
                                              attn, x, nullptr, Fn, Hn);

        float* lnout = (l == Ln - 1) ? (float*)d_out : x;
        ln_kernel<<<Mn, 256>>>(x, l2g + bOff, l2b + bOff, lnout,
                               (l == Ln - 1) ? nullptr : xh);
    }
}

// round 16
// speedup vs baseline: 1.5494x; 1.5494x over previous
#include <cuda_runtime.h>
#include <cuda_fp16.h>
#include <math.h>
#include <stdint.h>

// Problem constants
#define Bn 4
#define Sn 2048
#define Hn 512
#define NHn 8
#define DHn 64
#define Fn 2048
#define Ln 4
#define Mn (Bn * Sn)  // 8192
#define QKVS 1536
#define L2E 1.4426950408889634f

// ---------------- scratch (device globals; no allocation allowed) ----------
__device__ float g_x[Mn * Hn];
__device__ float g_attn[Mn * Hn];
__device__ __half g_sinv[(size_t)Bn * Sn * Sn];   // inv-scale * L2E (fp16)
__device__ float g_msk2[Bn * Sn];                 // mask * L2E

__device__ __half g_qkv[(size_t)Mn * QKVS];
__device__ __half g_ch[Mn * Hn];   // ctx
__device__ __half g_xh[Mn * Hn];
__device__ __half g_th[Mn * Hn];   // attn (post ln1)
__device__ __half g_fh[(size_t)Mn * Fn];

// weights (single fp16)
__device__ __half g_wqkv[Ln * Hn * QKVS];
__device__ __half g_wo[Ln * Hn * Hn];
__device__ __half g_wi[Ln * Hn * Fn];
__device__ __half g_w2[Ln * Fn * Hn];
__device__ float g_bqkv[Ln * QKVS];
__device__ __half g_pbb[(size_t)NHn * Sn * Sn];   // fp16 position bias * L2E

// ---------------- helpers ---------------------------------------------------
__device__ __forceinline__ uint32_t cvta_smem(const void* p) {
    uint32_t a;
    asm("{ .reg .u64 t; cvta.to.shared.u64 t, %1; cvt.u32.u64 %0, t; }"
        : "=r"(a) : "l"(p));
    return a;
}

#define CP16(dst, src) \
    asm volatile("cp.async.cg.shared.global [%0], [%1], 16;" :: "r"(dst), "l"(src))
#define CP_COMMIT() asm volatile("cp.async.commit_group;" ::: "memory")
#define CP_WAIT0()  asm volatile("cp.async.wait_group 0;" ::: "memory")
#define CP_WAIT1()  asm volatile("cp.async.wait_group 1;" ::: "memory")

#define LDSM4(r, addr)                                                          \
    asm volatile("ldmatrix.sync.aligned.m8n8.x4.shared.b16 {%0,%1,%2,%3}, [%4];"\
        : "=r"((r)[0]), "=r"((r)[1]), "=r"((r)[2]), "=r"((r)[3]) : "r"(addr))
#define LDSM4T(r01, r23, addr)                                                  \
    asm volatile("ldmatrix.sync.aligned.m8n8.x4.trans.shared.b16 {%0,%1,%2,%3}, [%4];"\
        : "=r"((r01)[0]), "=r"((r01)[1]), "=r"((r23)[0]), "=r"((r23)[1]) : "r"(addr))

__device__ __forceinline__ void mma16816(float* c, const uint32_t* a, const uint32_t* b) {
    asm volatile(
        "mma.sync.aligned.m16n8k16.row.col.f32.f16.f16.f32 "
        "{%0,%1,%2,%3}, {%4,%5,%6,%7}, {%8,%9}, {%0,%1,%2,%3};"
        : "+f"(c[0]), "+f"(c[1]), "+f"(c[2]), "+f"(c[3])
        : "r"(a[0]), "r"(a[1]), "r"(a[2]), "r"(a[3]), "r"(b[0]), "r"(b[1]));
}

__device__ __forceinline__ uint32_t pack_h2(float lo, float hi) {
    __half2 p = __floats2half2_rn(lo, hi);
    return *reinterpret_cast<uint32_t*>(&p);
}
__device__ __forceinline__ float h_lo(uint32_t u) {
    return __half2float(__ushort_as_half((unsigned short)(u & 0xffffu)));
}
__device__ __forceinline__ float h_hi(uint32_t u) {
    return __half2float(__ushort_as_half((unsigned short)(u >> 16)));
}
__device__ __forceinline__ float ex2f(float x) {
    float y;
    asm("ex2.approx.ftz.f32 %0, %1;" : "=f"(y) : "f"(x));
    return y;
}
__device__ __forceinline__ float rcpf(float x) {
    float y;
    asm("rcp.approx.ftz.f32 %0, %1;" : "=f"(y) : "f"(x));
    return y;
}
// 1/scale = (u + 60000) / (9u + 480000), u = max(dt_ms, 0)
__device__ __forceinline__ float sinv_of(int dt) {
    float u = fmaxf((float)dt, 0.0f);
    return (u + 60000.0f) * rcpf(fmaf(u, 9.0f, 480000.0f));
}

// convert 8 fp32 -> fp16x8 (scaled) and store
__device__ __forceinline__ void cvt8_store_s(
    const float* __restrict__ src, __half* __restrict__ h, float sc)
{
    float4 a = *(const float4*)src;
    float4 b = *(const float4*)(src + 4);
    float v[8] = {a.x, a.y, a.z, a.w, b.x, b.y, b.z, b.w};
    __align__(16) __half hh[8];
#pragma unroll
    for (int j = 0; j < 8; j++) hh[j] = __float2half_rn(v[j] * sc);
    *(uint4*)h = *(const uint4*)hh;
}
__device__ __forceinline__ void cvt8_store(
    const float* __restrict__ src, __half* __restrict__ h)
{
    cvt8_store_s(src, h, 1.0f);
}

// smem stage layout for dense GEMM: A 128x80B, B 32x272B
#define OFF_AH 0
#define OFF_BH 10240
#define STAGE_BYTES 18944   // x2 stages = 37888

// ---------------------------------------------------------------------------
__global__ void __launch_bounds__(256) cvt_h_kernel(
    const float* __restrict__ x, __half* __restrict__ y, int n, float sc)
{
    int i = (blockIdx.x * 256 + threadIdx.x) * 8;
    if (i >= n) return;
    cvt8_store_s(x + i, y + i, sc);
}

__global__ void __launch_bounds__(256) mask_kernel(
    const float* __restrict__ mask, float* __restrict__ out)
{
    int i = blockIdx.x * 256 + threadIdx.x;
    if (i < Bn * Sn) out[i] = mask[i] * L2E;
}

// sinv[b][q][k] = (1/scale)*L2E (fp16). One block per (b,q) row.
__global__ void __launch_bounds__(256) sinv_kernel(
    const int* __restrict__ ts, __half* __restrict__ sv)
{
    const int bq = blockIdx.x;
    const int b = bq >> 11;
    const int tq = ts[bq];
    const int* tr = ts + b * Sn;
    __half* out = sv + (size_t)bq * Sn;
#pragma unroll
    for (int kk = 0; kk < 2; kk++) {
        int k = (threadIdx.x + (kk << 8)) << 2;
        int4 tk = *(const int4*)(tr + k);
        uint2 o;
        o.x = pack_h2(sinv_of(tq - tk.x) * L2E, sinv_of(tq - tk.y) * L2E);
        o.y = pack_h2(sinv_of(tq - tk.z) * L2E, sinv_of(tq - tk.w) * L2E);
        *(uint2*)(out + k) = o;
    }
}

// ---------------------------------------------------------------------------
// Weight prep (fp16 cvt + qkv pack + bias pack)  (R13 version)
// ---------------------------------------------------------------------------
__global__ void __launch_bounds__(256) prep_kernel(
    const float* __restrict__ wq, const float* __restrict__ wk,
    const float* __restrict__ wv, const float* __restrict__ wo,
    const float* __restrict__ wi, const float* __restrict__ wo2,
    const float* __restrict__ bq, const float* __restrict__ bk,
    const float* __restrict__ bv,
    __half* __restrict__ wqkv, __half* __restrict__ woh,
    __half* __restrict__ wih, __half* __restrict__ w2h,
    float* __restrict__ bqkv)
{
    const int blk = blockIdx.x;
    if (blk < 1536) {
        const int seg = blk >> 9, b2 = blk & 511;
        const float* src = (seg == 0) ? wq : (seg == 1) ? wk : wv;
        const int coloff = seg << 9;
        const int i = (b2 * 256 + threadIdx.x) * 8;
        const int row = i >> 9, col = i & 511;
        cvt8_store(src + i, wqkv + (size_t)row * QKVS + coloff + col);
    } else if (blk < 2048) {
        const int i = ((blk - 1536) * 256 + threadIdx.x) * 8;
        cvt8_store(wo + i, woh + i);
    } else if (blk < 4096) {
        const int i = ((blk - 2048) * 256 + threadIdx.x) * 8;
        cvt8_store(wi + i, wih + i);
    } else if (blk < 6144) {
        const int i = ((blk - 4096) * 256 + threadIdx.x) * 8;
        cvt8_store(wo2 + i, w2h + i);
    } else {
        const int i0 = ((blk - 6144) * 256 + threadIdx.x) * 8;
#pragma unroll
        for (int j = 0; j < 8; j++) {
            const int idx = i0 + j;
            const int l = idx / QKVS, jj = idx % QKVS;
            const int seg = jj >> 9, col = jj & 511;
            const float* s = (seg == 0) ? bq : (seg == 1) ? bk : bv;
            bqkv[idx] = s[l * Hn + col];
        }
    }
}

// ---------------------------------------------------------------------------
// HMMA GEMM, single fp16, 1-pass: C = Ah*Wh.  CTA 128x128, BK=32, 8 warps.
// (R13 known-good version)
// ---------------------------------------------------------------------------
template <int EPI>
__global__ void __launch_bounds__(256, 2) hmma_gemm(
    const __half* __restrict__ Ahp, const __half* __restrict__ Bhp,
    const float* __restrict__ bias, const float* __restrict__ res,
    float* __restrict__ C, __half* __restrict__ Cho, int K, int N)
{
    extern __shared__ char smem[];
    const uint32_t sb = cvta_smem(smem);
    const int tid = threadIdx.x, lane = tid & 31, warp = tid >> 5;
    const int m0 = blockIdx.y << 7, n0 = blockIdx.x << 7;
    const int wm0 = (warp >> 2) << 6, wn0 = (warp & 3) << 5;

    const int ar = tid >> 2, ac = tid & 3;
    const int br = tid >> 4, bc = tid & 15;

    auto load_stage = [&](int st, int kc) {
        const int k0 = kc << 5;
        const uint32_t s = sb + st * STAGE_BYTES;
        const size_t aoff0 = (size_t)(m0 + ar) * K + k0 + ac * 8;
        const size_t aoff1 = (size_t)(m0 + ar + 64) * K + k0 + ac * 8;
        CP16(s + OFF_AH + ar * 80 + ac * 16, Ahp + aoff0);
        CP16(s + OFF_AH + (ar + 64) * 80 + ac * 16, Ahp + aoff1);
        const size_t boff0 = (size_t)(k0 + br) * N + n0 + bc * 8;
        const size_t boff1 = (size_t)(k0 + br + 16) * N + n0 + bc * 8;
        CP16(s + OFF_BH + br * 272 + bc * 16, Bhp + boff0);
        CP16(s + OFF_BH + (br + 16) * 272 + bc * 16, Bhp + boff1);
        CP_COMMIT();
    };

    float acc[4][4][4];
#pragma unroll
    for (int i = 0; i < 4; i++)
#pragma unroll
        for (int j = 0; j < 4; j++)
#pragma unroll
            for (int r = 0; r < 4; r++) acc[i][j][r] = 0.0f;

    const int nch = K >> 5;
    load_stage(0, 0);

    for (int kc = 0; kc < nch; kc++) {
        const int cur = kc & 1;
        CP_WAIT0();
        __syncthreads();
        if (kc + 1 < nch) load_stage(cur ^ 1, kc + 1);

        const uint32_t s = sb + cur * STAGE_BYTES;
#pragma unroll
        for (int ks = 0; ks < 2; ks++) {
            const uint32_t aoff =
                (wm0 + (lane & 15)) * 80 + ((ks << 4) + ((lane >> 4) << 3)) * 2;
            const uint32_t boff =
                ((ks << 4) + (lane & 15)) * 272 + (wn0 + ((lane >> 4) << 3)) * 2;

            uint32_t ah[4][4];
#pragma unroll
            for (int mt = 0; mt < 4; mt++)
                LDSM4(ah[mt], s + OFF_AH + aoff + mt * (16 * 80));
            uint32_t b[4][2];
            LDSM4T(b[0], b[1], s + OFF_BH + boff);
            LDSM4T(b[2], b[3], s + OFF_BH + boff + 32);
#pragma unroll
            for (int mt = 0; mt < 4; mt++)
#pragma unroll
                for (int nt = 0; nt < 4; nt++) mma16816(acc[mt][nt], ah[mt], b[nt]);
        }
    }

#pragma unroll
    for (int mt = 0; mt < 4; mt++) {
        const int m = m0 + wm0 + mt * 16 + (lane >> 2);
#pragma unroll
        for (int nt = 0; nt < 4; nt++) {
            const int n = n0 + wn0 + nt * 8 + (lane & 3) * 2;
            float2 bv = *(const float2*)(bias + n);
            float o0 = acc[mt][nt][0] + bv.x;
            float o1 = acc[mt][nt][1] + bv.y;
            float o2 = acc[mt][nt][2] + bv.x;
            float o3 = acc[mt][nt][3] + bv.y;
            if (EPI == 1) {
                float2 r0 = *(const float2*)(res + (size_t)m * N + n);
                float2 r1 = *(const float2*)(res + (size_t)(m + 8) * N + n);
                o0 += r0.x; o1 += r0.y; o2 += r1.x; o3 += r1.y;
                *(float2*)(C + (size_t)m * N + n) = make_float2(o0, o1);
                *(float2*)(C + (size_t)(m + 8) * N + n) = make_float2(o2, o3);
            } else {
                if (EPI == 2) {
                    o0 = 0.5f * o0 * (1.0f + erff(o0 * 0.7071067811865475f));
                    o1 = 0.5f * o1 * (1.0f + erff(o1 * 0.7071067811865475f));
                    o2 = 0.5f * o2 * (1.0f + erff(o2 * 0.7071067811865475f));
                    o3 = 0.5f * o3 * (1.0f + erff(o3 * 0.7071067811865475f));
                }
                *(uint32_t*)(Cho + (size_t)m * N + n) = pack_h2(o0, o1);
                *(uint32_t*)(Cho + (size_t)(m + 8) * N + n) = pack_h2(o2, o3);
            }
        }
    }
}

// ---------------------------------------------------------------------------
// Flash attention, fp16 1-pass, log2-domain scores, f32 ex2, branch-free.
// 2-stage KV pipeline. (R13 known-good version, UNCHANGED)
// ---------------------------------------------------------------------------
#define FSTG 18432
__global__ void __launch_bounds__(256, 2) flash_kernel(
    const __half* __restrict__ QKV,
    const __half* __restrict__ sinv, const __half* __restrict__ pbb,
    const float* __restrict__ msk2, __half* __restrict__ Ch)
{
    extern __shared__ char smem[];
    const uint32_t sb = cvta_smem(smem);
    const int tid = threadIdx.x, lane = tid & 31, warp = tid >> 5;
    const int qb = blockIdx.x << 7;
    const int bh = blockIdx.y, b = bh & 3, h = bh >> 2;
    const uint32_t sQ = sb;
    const uint32_t sKV = sb + 18432;

    // Q + stage 0
#pragma unroll
    for (int i = 0; i < 4; i++) {
        int idx = tid + (i << 8);
        int r = idx >> 3, c = idx & 7;
        size_t off = ((size_t)(b * Sn + qb + r)) * QKVS + h * 64 + c * 8;
        CP16(sQ + r * 144 + c * 16, QKV + off);
    }
#pragma unroll
    for (int i = 0; i < 2; i++) {
        int idx = tid + (i << 8);
        int r = idx >> 3, c = idx & 7;
        size_t off = ((size_t)(b * Sn + r)) * QKVS + h * 64 + c * 8;
        uint32_t d = sKV + r * 144 + c * 16;
        CP16(d, QKV + off + 512);           // K
        CP16(d + 9216, QKV + off + 1024);   // V
    }
    CP_COMMIT();

    const int qr0 = qb + (warp << 4) + (lane >> 2);
    const __half* sv0 = sinv + ((size_t)(b * Sn + qr0)) * Sn;
    const __half* sv1 = sv0 + (size_t)8 * Sn;
    const __half* pb0 = pbb + ((size_t)(h * Sn + qr0)) * Sn;
    const __half* pb1 = pb0 + (size_t)8 * Sn;
    const float* mrow = msk2 + b * Sn;

    float oacc[8][4];
#pragma unroll
    for (int t = 0; t < 8; t++)
#pragma unroll
        for (int r = 0; r < 4; r++) oacc[t][r] = 0.0f;
    float m0 = -1e30f, m1 = -1e30f, l0 = 0.0f, l1 = 0.0f;

    for (int it = 0; it < 32; it++) {
        if (it + 1 < 32) {
            const uint32_t s = sKV + ((it + 1) & 1) * FSTG;
            const int k0n = (it + 1) << 6;
#pragma unroll
            for (int i = 0; i < 2; i++) {
                int idx = tid + (i << 8);
                int r = idx >> 3, c = idx & 7;
                size_t off = ((size_t)(b * Sn + k0n + r)) * QKVS + h * 64 + c * 8;
                uint32_t d = s + r * 144 + c * 16;
                CP16(d, QKV + off + 512);
                CP16(d + 9216, QKV + off + 1024);
            }
        }
        CP_COMMIT();
        CP_WAIT1();
        __syncthreads();

        const uint32_t stg = sKV + (it & 1) * FSTG;
        float sacc[8][4];
#pragma unroll
        for (int t = 0; t < 8; t++)
#pragma unroll
            for (int r = 0; r < 4; r++) sacc[t][r] = 0.0f;

        // S = Qh * Kh
#pragma unroll
        for (int kc = 0; kc < 4; kc++) {
            uint32_t aq[4];
            const uint32_t qa = sQ + ((warp << 4) + (lane & 15)) * 144 +
                                ((kc << 4) + ((lane >> 4) << 3)) * 2;
            LDSM4(aq, qa);
#pragma unroll
            for (int nb = 0; nb < 4; nb++) {
                uint32_t kb[4];
                const uint32_t ka = stg + ((nb << 4) + (lane & 15)) * 144 +
                                    ((kc << 4) + ((lane >> 4) << 3)) * 2;
                LDSM4(kb, ka);
#pragma unroll
                for (int tt = 0; tt < 2; tt++) {
                    const int t = (nb << 1) + tt;
                    uint32_t b_[2] = {kb[tt], kb[tt + 2]};
                    mma16816(sacc[t], aq, b_);
                }
            }
        }

        // scoring (log2 domain): s = qk*sinv2 + pb2 + mk2, online softmax
        const int k0 = it << 6;
        float tm0 = -1e30f, tm1 = -1e30f;
#pragma unroll
        for (int t = 0; t < 8; t++) {
            const int n = k0 + (t << 3) + ((lane & 3) << 1);
            uint32_t su0 = *(const uint32_t*)(sv0 + n);
            uint32_t su1 = *(const uint32_t*)(sv1 + n);
            float2 mk = *(const float2*)(mrow + n);
            uint32_t pu0 = *(const uint32_t*)(pb0 + n);
            uint32_t pu1 = *(const uint32_t*)(pb1 + n);
            sacc[t][0] = fmaf(sacc[t][0], h_lo(su0), h_lo(pu0) + mk.x);
            sacc[t][1] = fmaf(sacc[t][1], h_hi(su0), h_hi(pu0) + mk.y);
            sacc[t][2] = fmaf(sacc[t][2], h_lo(su1), h_lo(pu1) + mk.x);
            sacc[t][3] = fmaf(sacc[t][3], h_hi(su1), h_hi(pu1) + mk.y);
            tm0 = fmaxf(tm0, fmaxf(sacc[t][0], sacc[t][1]));
            tm1 = fmaxf(tm1, fmaxf(sacc[t][2], sacc[t][3]));
        }
        tm0 = fmaxf(tm0, __shfl_xor_sync(0xffffffffu, tm0, 1));
        tm0 = fmaxf(tm0, __shfl_xor_sync(0xffffffffu, tm0, 2));
        tm1 = fmaxf(tm1, __shfl_xor_sync(0xffffffffu, tm1, 1));
        tm1 = fmaxf(tm1, __shfl_xor_sync(0xffffffffu, tm1, 2));
        const float mn0 = fmaxf(m0, tm0), mn1 = fmaxf(m1, tm1);
        const float c0 = ex2f(m0 - mn0), c1 = ex2f(m1 - mn1);
        m0 = mn0; m1 = mn1;

        float rs0 = 0.0f, rs1 = 0.0f;
        uint32_t ap[4][4];
#pragma unroll
        for (int t = 0; t < 8; t++) {
            float p00 = ex2f(sacc[t][0] - m0);
            float p01 = ex2f(sacc[t][1] - m0);
            float p10 = ex2f(sacc[t][2] - m1);
            float p11 = ex2f(sacc[t][3] - m1);
            rs0 += p00 + p01; rs1 += p10 + p11;
            const int kc2 = t >> 1, hf = (t & 1) << 1;
            ap[kc2][hf] = pack_h2(p00, p01);
            ap[kc2][hf + 1] = pack_h2(p10, p11);
        }
        rs0 += __shfl_xor_sync(0xffffffffu, rs0, 1);
        rs0 += __shfl_xor_sync(0xffffffffu, rs0, 2);
        rs1 += __shfl_xor_sync(0xffffffffu, rs1, 1);
        rs1 += __shfl_xor_sync(0xffffffffu, rs1, 2);
        l0 = l0 * c0 + rs0;
        l1 = l1 * c1 + rs1;
#pragma unroll
        for (int t = 0; t < 8; t++) {
            oacc[t][0] *= c0; oacc[t][1] *= c0;
            oacc[t][2] *= c1; oacc[t][3] *= c1;
        }

        // O += Ph * Vh
#pragma unroll
        for (int kc2 = 0; kc2 < 4; kc2++) {
#pragma unroll
            for (int dnb = 0; dnb < 4; dnb++) {
                uint32_t vf[2][2];
                const uint32_t va = stg + 9216 +
                    ((kc2 << 4) + (lane & 15)) * 144 +
                    ((dnb << 4) + ((lane >> 4) << 3)) * 2;
                LDSM4T(vf[0], vf[1], va);
#pragma unroll
                for (int tt = 0; tt < 2; tt++)
                    mma16816(oacc[(dnb << 1) + tt], ap[kc2], vf[tt]);
            }
        }
        __syncthreads();
    }

    const float inv0 = 1.0f / l0, inv1 = 1.0f / l1;
#pragma unroll
    for (int t = 0; t < 8; t++) {
        const int d = (t << 3) + ((lane & 3) << 1);
        const size_t o0 = ((size_t)(b * Sn + qr0)) * Hn + h * 64 + d;
        const size_t o1 = ((size_t)(b * Sn + qr0 + 8)) * Hn + h * 64 + d;
        *(uint32_t*)(Ch + o0) = pack_h2(oacc[t][0] * inv0, oacc[t][1] * inv0);
        *(uint32_t*)(Ch + o1) = pack_h2(oacc[t][2] * inv1, oacc[t][3] * inv1);
    }
}

// ---------------------------------------------------------------------------
// LayerNorm over H=512: one WARP per row, 8 rows per 256-thread block.
// Pure warp shuffles — no smem, no __syncthreads.
// ---------------------------------------------------------------------------
__global__ void __launch_bounds__(256) ln_kernel(
    const float* __restrict__ in, const float* __restrict__ g,
    const float* __restrict__ bta, float* __restrict__ out,
    __half* __restrict__ ho)
{
    const int warp = threadIdx.x >> 5, lane = threadIdx.x & 31;
    const size_t base = ((size_t)blockIdx.x * 8 + warp) * Hn;
    float v[16];
    float s = 0.0f;
#pragma unroll
    for (int i = 0; i < 4; i++) {
        float4 t = *(const float4*)(in + base + (i << 7) + (lane << 2));
        v[i * 4 + 0] = t.x; v[i * 4 + 1] = t.y;
        v[i * 4 + 2] = t.z; v[i * 4 + 3] = t.w;
        s += t.x + t.y + t.z + t.w;
    }
#pragma unroll
    for (int o = 16; o; o >>= 1) s += __shfl_xor_sync(0xffffffffu, s, o);
    const float mean = s * (1.0f / Hn);
    float vv = 0.0f;
#pragma unroll
    for (int j = 0; j < 16; j++) {
        v[j] -= mean;
        vv = fmaf(v[j], v[j], vv);
    }
#pragma unroll
    for (int o = 16; o; o >>= 1) vv += __shfl_xor_sync(0xffffffffu, vv, o);
    const float inv = rsqrtf(vv * (1.0f / Hn) + 1e-12f);
#pragma unroll
    for (int i = 0; i < 4; i++) {
        const int col = (i << 7) + (lane << 2);
        float4 gv = *(const float4*)(g + col);
        float4 bv = *(const float4*)(bta + col);
        float y0 = v[i * 4 + 0] * inv * gv.x + bv.x;
        float y1 = v[i * 4 + 1] * inv * gv.y + bv.y;
        float y2 = v[i * 4 + 2] * inv * gv.z + bv.z;
        float y3 = v[i * 4 + 3] * inv * gv.w + bv.w;
        *(float4*)(out + base + col) = make_float4(y0, y1, y2, y3);
        if (ho) {
            uint2 p;
            p.x = pack_h2(y0, y1);
            p.y = pack_h2(y2, y3);
            *(uint2*)(ho + base + col) = p;
        }
    }
}

// ---------------------------------------------------------------------------
extern "C" void kernel_launch(void* const* d_in, const int* in_sizes, int n_in,
                              void* d_out, int out_size)
{
    (void)in_sizes; (void)n_in; (void)out_size;
    const float* qs   = (const float*)d_in[0];
    const float* mask = (const float*)d_in[1];
    const float* pb   = (const float*)d_in[2];
    const int*   ts   = (const int*)d_in[3];
    const float* wq  = (const float*)d_in[4];  const float* bq  = (const float*)d_in[5];
    const float* wk  = (const float*)d_in[6];  const float* bk  = (const float*)d_in[7];
    const float* wv  = (const float*)d_in[8];  const float* bv  = (const float*)d_in[9];
    const float* wo  = (const float*)d_in[10]; const float* bo  = (const float*)d_in[11];
    const float* l1g = (const float*)d_in[12]; const float* l1b = (const float*)d_in[13];
    const float* wi  = (const float*)d_in[14]; const float* bi  = (const float*)d_in[15];
    const float* wo2 = (const float*)d_in[16]; const float* bo2 = (const float*)d_in[17];
    const float* l2g = (const float*)d_in[18]; const float* l2b = (const float*)d_in[19];

    float *x, *attn, *bqkv, *msk2;
    cudaGetSymbolAddress((void**)&x,    g_x);
    cudaGetSymbolAddress((void**)&attn, g_attn);
    cudaGetSymbolAddress((void**)&bqkv, g_bqkv);
    cudaGetSymbolAddress((void**)&msk2, g_msk2);

    __half *qkv, *ch, *xh, *th, *fh, *pbb, *sinvp;
    cudaGetSymbolAddress((void**)&qkv, g_qkv);
    cudaGetSymbolAddress((void**)&ch, g_ch);
    cudaGetSymbolAddress((void**)&xh, g_xh);
    cudaGetSymbolAddress((void**)&th, g_th);
    cudaGetSymbolAddress((void**)&fh, g_fh);
    cudaGetSymbolAddress((void**)&pbb, g_pbb);
    cudaGetSymbolAddress((void**)&sinvp, g_sinv);

    __half *wqkvp, *wop, *wip, *w2p;
    cudaGetSymbolAddress((void**)&wqkvp, g_wqkv);
    cudaGetSymbolAddress((void**)&wop, g_wo);
    cudaGetSymbolAddress((void**)&wip, g_wi);
    cudaGetSymbolAddress((void**)&w2p, g_w2);

    const int HM_SMEM = 2 * STAGE_BYTES;  // 37888
    const int FL_SMEM = 18432 + 2 * FSTG; // 55296
    cudaFuncSetAttribute(hmma_gemm<0>, cudaFuncAttributeMaxDynamicSharedMemorySize, HM_SMEM);
    cudaFuncSetAttribute(hmma_gemm<1>, cudaFuncAttributeMaxDynamicSharedMemorySize, HM_SMEM);
    cudaFuncSetAttribute(hmma_gemm<2>, cudaFuncAttributeMaxDynamicSharedMemorySize, HM_SMEM);
    cudaFuncSetAttribute(flash_kernel, cudaFuncAttributeMaxDynamicSharedMemorySize, FL_SMEM);

    const int PBN = NHn * Sn * Sn;
    prep_kernel<<<6147, 256>>>(wq, wk, wv, wo, wi, wo2, bq, bk, bv,
                               wqkvp, wop, wip, w2p, bqkv);
    cvt_h_kernel<<<PBN / 2048, 256>>>(pb, pbb, PBN, L2E);
    sinv_kernel<<<Bn * Sn, 256>>>(ts, sinvp);
    mask_kernel<<<(Bn * Sn + 255) / 256, 256>>>(mask, msk2);
    cvt_h_kernel<<<(Mn * Hn) / 2048, 256>>>(qs, xh, Mn * Hn, 1.0f);

    dim3 gqkv(QKVS / 128, Mn / 128);  // (12, 64)
    dim3 gproj(Hn / 128, Mn / 128);   // (4, 64)
    dim3 gff(Fn / 128, Mn / 128);     // (16, 64)
    dim3 gfl(Sn / 128, Bn * NHn);     // (16, 32)

    for (int l = 0; l < Ln; l++) {
        const size_t wOff  = (size_t)l * Hn * Hn;
        const size_t bOff  = (size_t)l * Hn;
        const size_t wiOff = (size_t)l * Hn * Fn;
        const size_t biOff = (size_t)l * Fn;
        const float* xres = (l == 0) ? qs : x;

        hmma_gemm<0><<<gqkv, 256, HM_SMEM>>>(xh,
            wqkvp + (size_t)l * Hn * QKVS, bqkv + l * QKVS,
            nullptr, nullptr, qkv, Hn, QKVS);

        flash_kernel<<<gfl, 256, FL_SMEM>>>(qkv, sinvp, pbb, msk2, ch);

        hmma_gemm<1><<<gproj, 256, HM_SMEM>>>(ch, wop + wOff, bo + bOff,
                                              xres, attn, nullptr, Hn, Hn);
        ln_kernel<<<Mn / 8, 256>>>(attn, l1g + bOff, l1b + bOff, attn, th);

        hmma_gemm<2><<<gff, 256, HM_SMEM>>>(th, wip + wiOff, bi + biOff,
                                            nullptr, nullptr, fh, Hn, Fn);
        hmma_gemm<1><<<gproj, 256, HM_SMEM>>>(fh, w2p + wiOff, bo2 + bOff,
                                              attn, x, nullptr, Fn, Hn);

        float* lnout = (l == Ln - 1) ? (float*)d_out : x;
        ln_kernel<<<Mn / 8, 256>>>(x, l2g + bOff, l2b + bOff, lnout,
                                   (l == Ln - 1) ? nullptr : xh);
    }
}

// round 17
// speedup vs baseline: 1.6415x; 1.0594x over previous
#include <cuda_runtime.h>
#include <cuda_fp16.h>
#include <math.h>
#include <stdint.h>

// Problem constants
#define Bn 4
#define Sn 2048
#define Hn 512
#define NHn 8
#define DHn 64
#define Fn 2048
#define Ln 4
#define Mn (Bn * Sn)  // 8192
#define QKVS 1536
#define L2E 1.4426950408889634f

// ---------------- scratch (device globals; no allocation allowed) ----------
__device__ float g_x[Mn * Hn];
__device__ float g_attn[Mn * Hn];
__device__ __half2 g_aux[(size_t)Bn * NHn * Sn * Sn];  // 536 MB fused epilogue aux

__device__ __half g_qkv[(size_t)Mn * QKVS];
__device__ __half g_ch[Mn * Hn];   // ctx
__device__ __half g_xh[Mn * Hn];
__device__ __half g_th[Mn * Hn];   // attn (post ln1)
__device__ __half g_fh[(size_t)Mn * Fn];

// weights (single fp16)
__device__ __half g_wqkv[Ln * Hn * QKVS];
__device__ __half g_wo[Ln * Hn * Hn];
__device__ __half g_wi[Ln * Hn * Fn];
__device__ __half g_w2[Ln * Fn * Hn];
__device__ float g_bqkv[Ln * QKVS];

// ---------------- helpers ---------------------------------------------------
__device__ __forceinline__ uint32_t cvta_smem(const void* p) {
    uint32_t a;
    asm("{ .reg .u64 t; cvta.to.shared.u64 t, %1; cvt.u32.u64 %0, t; }"
        : "=r"(a) : "l"(p));
    return a;
}

#define CP16(dst, src) \
    asm volatile("cp.async.cg.shared.global [%0], [%1], 16;" :: "r"(dst), "l"(src))
#define CP_COMMIT() asm volatile("cp.async.commit_group;" ::: "memory")
#define CP_WAIT0()  asm volatile("cp.async.wait_group 0;" ::: "memory")
#define CP_WAIT1()  asm volatile("cp.async.wait_group 1;" ::: "memory")

#define LDSM4(r, addr)                                                          \
    asm volatile("ldmatrix.sync.aligned.m8n8.x4.shared.b16 {%0,%1,%2,%3}, [%4];"\
        : "=r"((r)[0]), "=r"((r)[1]), "=r"((r)[2]), "=r"((r)[3]) : "r"(addr))
#define LDSM4T(r01, r23, addr)                                                  \
    asm volatile("ldmatrix.sync.aligned.m8n8.x4.trans.shared.b16 {%0,%1,%2,%3}, [%4];"\
        : "=r"((r01)[0]), "=r"((r01)[1]), "=r"((r23)[0]), "=r"((r23)[1]) : "r"(addr))

__device__ __forceinline__ void mma16816(float* c, const uint32_t* a, const uint32_t* b) {
    asm volatile(
        "mma.sync.aligned.m16n8k16.row.col.f32.f16.f16.f32 "
        "{%0,%1,%2,%3}, {%4,%5,%6,%7}, {%8,%9}, {%0,%1,%2,%3};"
        : "+f"(c[0]), "+f"(c[1]), "+f"(c[2]), "+f"(c[3])
        : "r"(a[0]), "r"(a[1]), "r"(a[2]), "r"(a[3]), "r"(b[0]), "r"(b[1]));
}

__device__ __forceinline__ uint32_t pack_h2(float lo, float hi) {
    __half2 p = __floats2half2_rn(lo, hi);
    return *reinterpret_cast<uint32_t*>(&p);
}
__device__ __forceinline__ float h_lo(uint32_t u) {
    return __half2float(__ushort_as_half((unsigned short)(u & 0xffffu)));
}
__device__ __forceinline__ float h_hi(uint32_t u) {
    return __half2float(__ushort_as_half((unsigned short)(u >> 16)));
}
__device__ __forceinline__ float ex2f(float x) {
    float y;
    asm("ex2.approx.ftz.f32 %0, %1;" : "=f"(y) : "f"(x));
    return y;
}
__device__ __forceinline__ float rcpf(float x) {
    float y;
    asm("rcp.approx.ftz.f32 %0, %1;" : "=f"(y) : "f"(x));
    return y;
}
// 1/scale = (u + 60000) / (9u + 480000), u = max(dt_ms, 0)
__device__ __forceinline__ float sinv_of(int dt) {
    float u = fmaxf((float)dt, 0.0f);
    return (u + 60000.0f) * rcpf(fmaf(u, 9.0f, 480000.0f));
}

// convert 8 fp32 -> fp16x8 and store
__device__ __forceinline__ void cvt8_store(
    const float* __restrict__ src, __half* __restrict__ h)
{
    float4 a = *(const float4*)src;
    float4 b = *(const float4*)(src + 4);
    float v[8] = {a.x, a.y, a.z, a.w, b.x, b.y, b.z, b.w};
    __align__(16) __half hh[8];
#pragma unroll
    for (int j = 0; j < 8; j++) hh[j] = __float2half_rn(v[j]);
    *(uint4*)h = *(const uint4*)hh;
}

// smem stage layout for dense GEMM: A 128x80B, B 32x272B
#define OFF_AH 0
#define OFF_BH 10240
#define STAGE_BYTES 18944   // x2 stages = 37888

// ---------------------------------------------------------------------------
__global__ void __launch_bounds__(256) cvt_h_kernel(
    const float* __restrict__ x, __half* __restrict__ y, int n)
{
    int i = (blockIdx.x * 256 + threadIdx.x) * 8;
    if (i >= n) return;
    cvt8_store(x + i, y + i);
}

// ---------------------------------------------------------------------------
// aux[b][h][q][k] = half2( sinv(b,q,k)*L2E , pb(h,q,k)*L2E + mask(b,k)*L2E )
// One block per (b,q) row; each thread handles 8 k for all 8 heads.
// ---------------------------------------------------------------------------
__global__ void __launch_bounds__(256) aux_kernel(
    const int* __restrict__ ts, const float* __restrict__ pb,
    const float* __restrict__ mask, __half2* __restrict__ aux)
{
    const int bq = blockIdx.x;            // 8192 = (b, q)
    const int b = bq >> 11, q = bq & 2047;
    const int tq = ts[bq];
    const int k0 = threadIdx.x << 3;
    const int* tr = ts + b * Sn;

    int4 t0 = *(const int4*)(tr + k0);
    int4 t1 = *(const int4*)(tr + k0 + 4);
    int tk[8] = {t0.x, t0.y, t0.z, t0.w, t1.x, t1.y, t1.z, t1.w};
    float4 m0 = *(const float4*)(mask + b * Sn + k0);
    float4 m1 = *(const float4*)(mask + b * Sn + k0 + 4);
    float mm[8] = {m0.x, m0.y, m0.z, m0.w, m1.x, m1.y, m1.z, m1.w};
    float sv[8];
#pragma unroll
    for (int j = 0; j < 8; j++) {
        sv[j] = sinv_of(tq - tk[j]) * L2E;
        mm[j] *= L2E;
    }
#pragma unroll
    for (int h = 0; h < NHn; h++) {
        const float* pbr = pb + ((size_t)(h * Sn + q)) * Sn + k0;
        float4 p0 = *(const float4*)pbr;
        float4 p1 = *(const float4*)(pbr + 4);
        float pp[8] = {p0.x, p0.y, p0.z, p0.w, p1.x, p1.y, p1.z, p1.w};
        __align__(16) uint32_t o[8];
#pragma unroll
        for (int j = 0; j < 8; j++)
            o[j] = pack_h2(sv[j], fmaf(pp[j], L2E, mm[j]));
        __half2* dst = aux + (((size_t)((b << 3) + h) * Sn + q)) * Sn + k0;
        *(uint4*)dst = *(const uint4*)o;
        *(uint4*)(dst + 4) = *(const uint4*)(o + 4);
    }
}

// ---------------------------------------------------------------------------
// Weight prep (fp16 cvt + qkv pack + bias pack)  (R13 version)
// ---------------------------------------------------------------------------
__global__ void __launch_bounds__(256) prep_kernel(
    const float* __restrict__ wq, const float* __restrict__ wk,
    const float* __restrict__ wv, const float* __restrict__ wo,
    const float* __restrict__ wi, const float* __restrict__ wo2,
    const float* __restrict__ bq, const float* __restrict__ bk,
    const float* __restrict__ bv,
    __half* __restrict__ wqkv, __half* __restrict__ woh,
    __half* __restrict__ wih, __half* __restrict__ w2h,
    float* __restrict__ bqkv)
{
    const int blk = blockIdx.x;
    if (blk < 1536) {
        const int seg = blk >> 9, b2 = blk & 511;
        const float* src = (seg == 0) ? wq : (seg == 1) ? wk : wv;
        const int coloff = seg << 9;
        const int i = (b2 * 256 + threadIdx.x) * 8;
        const int row = i >> 9, col = i & 511;
        cvt8_store(src + i, wqkv + (size_t)row * QKVS + coloff + col);
    } else if (blk < 2048) {
        const int i = ((blk - 1536) * 256 + threadIdx.x) * 8;
        cvt8_store(wo + i, woh + i);
    } else if (blk < 4096) {
        const int i = ((blk - 2048) * 256 + threadIdx.x) * 8;
        cvt8_store(wi + i, wih + i);
    } else if (blk < 6144) {
        const int i = ((blk - 4096) * 256 + threadIdx.x) * 8;
        cvt8_store(wo2 + i, w2h + i);
    } else {
        const int i0 = ((blk - 6144) * 256 + threadIdx.x) * 8;
#pragma unroll
        for (int j = 0; j < 8; j++) {
            const int idx = i0 + j;
            const int l = idx / QKVS, jj = idx % QKVS;
            const int seg = jj >> 9, col = jj & 511;
            const float* s = (seg == 0) ? bq : (seg == 1) ? bk : bv;
            bqkv[idx] = s[l * Hn + col];
        }
    }
}

// ---------------------------------------------------------------------------
// HMMA GEMM, single fp16, 1-pass: C = Ah*Wh.  CTA 128x128, BK=32, 8 warps.
// (R13 known-good version)
// ---------------------------------------------------------------------------
template <int EPI>
__global__ void __launch_bounds__(256, 2) hmma_gemm(
    const __half* __restrict__ Ahp, const __half* __restrict__ Bhp,
    const float* __restrict__ bias, const float* __restrict__ res,
    float* __restrict__ C, __half* __restrict__ Cho, int K, int N)
{
    extern __shared__ char smem[];
    const uint32_t sb = cvta_smem(smem);
    const int tid = threadIdx.x, lane = tid & 31, warp = tid >> 5;
    const int m0 = blockIdx.y << 7, n0 = blockIdx.x << 7;
    const int wm0 = (warp >> 2) << 6, wn0 = (warp & 3) << 5;

    const int ar = tid >> 2, ac = tid & 3;
    const int br = tid >> 4, bc = tid & 15;

    auto load_stage = [&](int st, int kc) {
        const int k0 = kc << 5;
        const uint32_t s = sb + st * STAGE_BYTES;
        const size_t aoff0 = (size_t)(m0 + ar) * K + k0 + ac * 8;
        const size_t aoff1 = (size_t)(m0 + ar + 64) * K + k0 + ac * 8;
        CP16(s + OFF_AH + ar * 80 + ac * 16, Ahp + aoff0);
        CP16(s + OFF_AH + (ar + 64) * 80 + ac * 16, Ahp + aoff1);
        const size_t boff0 = (size_t)(k0 + br) * N + n0 + bc * 8;
        const size_t boff1 = (size_t)(k0 + br + 16) * N + n0 + bc * 8;
        CP16(s + OFF_BH + br * 272 + bc * 16, Bhp + boff0);
        CP16(s + OFF_BH + (br + 16) * 272 + bc * 16, Bhp + boff1);
        CP_COMMIT();
    };

    float acc[4][4][4];
#pragma unroll
    for (int i = 0; i < 4; i++)
#pragma unroll
        for (int j = 0; j < 4; j++)
#pragma unroll
            for (int r = 0; r < 4; r++) acc[i][j][r] = 0.0f;

    const int nch = K >> 5;
    load_stage(0, 0);

    for (int kc = 0; kc < nch; kc++) {
        const int cur = kc & 1;
        CP_WAIT0();
        __syncthreads();
        if (kc + 1 < nch) load_stage(cur ^ 1, kc + 1);

        const uint32_t s = sb + cur * STAGE_BYTES;
#pragma unroll
        for (int ks = 0; ks < 2; ks++) {
            const uint32_t aoff =
                (wm0 + (lane & 15)) * 80 + ((ks << 4) + ((lane >> 4) << 3)) * 2;
            const uint32_t boff =
                ((ks << 4) + (lane & 15)) * 272 + (wn0 + ((lane >> 4) << 3)) * 2;

            uint32_t ah[4][4];
#pragma unroll
            for (int mt = 0; mt < 4; mt++)
                LDSM4(ah[mt], s + OFF_AH + aoff + mt * (16 * 80));
            uint32_t b[4][2];
            LDSM4T(b[0], b[1], s + OFF_BH + boff);
            LDSM4T(b[2], b[3], s + OFF_BH + boff + 32);
#pragma unroll
            for (int mt = 0; mt < 4; mt++)
#pragma unroll
                for (int nt = 0; nt < 4; nt++) mma16816(acc[mt][nt], ah[mt], b[nt]);
        }
    }

#pragma unroll
    for (int mt = 0; mt < 4; mt++) {
        const int m = m0 + wm0 + mt * 16 + (lane >> 2);
#pragma unroll
        for (int nt = 0; nt < 4; nt++) {
            const int n = n0 + wn0 + nt * 8 + (lane & 3) * 2;
            float2 bv = *(const float2*)(bias + n);
            float o0 = acc[mt][nt][0] + bv.x;
            float o1 = acc[mt][nt][1] + bv.y;
            float o2 = acc[mt][nt][2] + bv.x;
            float o3 = acc[mt][nt][3] + bv.y;
            if (EPI == 1) {
                float2 r0 = *(const float2*)(res + (size_t)m * N + n);
                float2 r1 = *(const float2*)(res + (size_t)(m + 8) * N + n);
                o0 += r0.x; o1 += r0.y; o2 += r1.x; o3 += r1.y;
                *(float2*)(C + (size_t)m * N + n) = make_float2(o0, o1);
                *(float2*)(C + (size_t)(m + 8) * N + n) = make_float2(o2, o3);
            } else {
                if (EPI == 2) {
                    o0 = 0.5f * o0 * (1.0f + erff(o0 * 0.7071067811865475f));
                    o1 = 0.5f * o1 * (1.0f + erff(o1 * 0.7071067811865475f));
                    o2 = 0.5f * o2 * (1.0f + erff(o2 * 0.7071067811865475f));
                    o3 = 0.5f * o3 * (1.0f + erff(o3 * 0.7071067811865475f));
                }
                *(uint32_t*)(Cho + (size_t)m * N + n) = pack_h2(o0, o1);
                *(uint32_t*)(Cho + (size_t)(m + 8) * N + n) = pack_h2(o2, o3);
            }
        }
    }
}

// ---------------------------------------------------------------------------
// Flash attention, fp16 1-pass, log2-domain, f32 ex2, branch-free.
// Epilogue aux fused into one half2 stream: 2 LDG.64 per t-step.
// ---------------------------------------------------------------------------
#define FSTG 18432
__global__ void __launch_bounds__(256, 2) flash_kernel(
    const __half* __restrict__ QKV, const __half2* __restrict__ aux,
    __half* __restrict__ Ch)
{
    extern __shared__ char smem[];
    const uint32_t sb = cvta_smem(smem);
    const int tid = threadIdx.x, lane = tid & 31, warp = tid >> 5;
    const int qb = blockIdx.x << 7;
    const int bh = blockIdx.y, b = bh & 3, h = bh >> 2;
    const uint32_t sQ = sb;
    const uint32_t sKV = sb + 18432;

    // Q + stage 0
#pragma unroll
    for (int i = 0; i < 4; i++) {
        int idx = tid + (i << 8);
        int r = idx >> 3, c = idx & 7;
        size_t off = ((size_t)(b * Sn + qb + r)) * QKVS + h * 64 + c * 8;
        CP16(sQ + r * 144 + c * 16, QKV + off);
    }
#pragma unroll
    for (int i = 0; i < 2; i++) {
        int idx = tid + (i << 8);
        int r = idx >> 3, c = idx & 7;
        size_t off = ((size_t)(b * Sn + r)) * QKVS + h * 64 + c * 8;
        uint32_t d = sKV + r * 144 + c * 16;
        CP16(d, QKV + off + 512);           // K
        CP16(d + 9216, QKV + off + 1024);   // V
    }
    CP_COMMIT();

    const int qr0 = qb + (warp << 4) + (lane >> 2);
    const __half2* ax0 = aux + (((size_t)((b << 3) + h) * Sn + qr0)) * Sn;
    const __half2* ax1 = ax0 + (size_t)8 * Sn;

    float oacc[8][4];
#pragma unroll
    for (int t = 0; t < 8; t++)
#pragma unroll
        for (int r = 0; r < 4; r++) oacc[t][r] = 0.0f;
    float m0 = -1e30f, m1 = -1e30f, l0 = 0.0f, l1 = 0.0f;

    for (int it = 0; it < 32; it++) {
        if (it + 1 < 32) {
            const uint32_t s = sKV + ((it + 1) & 1) * FSTG;
            const int k0n = (it + 1) << 6;
#pragma unroll
            for (int i = 0; i < 2; i++) {
                int idx = tid + (i << 8);
                int r = idx >> 3, c = idx & 7;
                size_t off = ((size_t)(b * Sn + k0n + r)) * QKVS + h * 64 + c * 8;
                uint32_t d = s + r * 144 + c * 16;
                CP16(d, QKV + off + 512);
                CP16(d + 9216, QKV + off + 1024);
            }
        }
        CP_COMMIT();
        CP_WAIT1();
        __syncthreads();

        const uint32_t stg = sKV + (it & 1) * FSTG;
        float sacc[8][4];
#pragma unroll
        for (int t = 0; t < 8; t++)
#pragma unroll
            for (int r = 0; r < 4; r++) sacc[t][r] = 0.0f;

        // S = Qh * Kh
#pragma unroll
        for (int kc = 0; kc < 4; kc++) {
            uint32_t aq[4];
            const uint32_t qa = sQ + ((warp << 4) + (lane & 15)) * 144 +
                                ((kc << 4) + ((lane >> 4) << 3)) * 2;
            LDSM4(aq, qa);
#pragma unroll
            for (int nb = 0; nb < 4; nb++) {
                uint32_t kb[4];
                const uint32_t ka = stg + ((nb << 4) + (lane & 15)) * 144 +
                                    ((kc << 4) + ((lane >> 4) << 3)) * 2;
                LDSM4(kb, ka);
#pragma unroll
                for (int tt = 0; tt < 2; tt++) {
                    const int t = (nb << 1) + tt;
                    uint32_t b_[2] = {kb[tt], kb[tt + 2]};
                    mma16816(sacc[t], aq, b_);
                }
            }
        }

        // scoring (log2 domain): s = qk*sinv2 + (pb2+mk2), online softmax
        const int k0 = it << 6;
        float tm0 = -1e30f, tm1 = -1e30f;
#pragma unroll
        for (int t = 0; t < 8; t++) {
            const int n = k0 + (t << 3) + ((lane & 3) << 1);
            uint2 a0 = *(const uint2*)(ax0 + n);
            uint2 a1 = *(const uint2*)(ax1 + n);
            sacc[t][0] = fmaf(sacc[t][0], h_lo(a0.x), h_hi(a0.x));
            sacc[t][1] = fmaf(sacc[t][1], h_lo(a0.y), h_hi(a0.y));
            sacc[t][2] = fmaf(sacc[t][2], h_lo(a1.x), h_hi(a1.x));
            sacc[t][3] = fmaf(sacc[t][3], h_lo(a1.y), h_hi(a1.y));
            tm0 = fmaxf(tm0, fmaxf(sacc[t][0], sacc[t][1]));
            tm1 = fmaxf(tm1, fmaxf(sacc[t][2], sacc[t][3]));
        }
        tm0 = fmaxf(tm0, __shfl_xor_sync(0xffffffffu, tm0, 1));
        tm0 = fmaxf(tm0, __shfl_xor_sync(0xffffffffu, tm0, 2));
        tm1 = fmaxf(tm1, __shfl_xor_sync(0xffffffffu, tm1, 1));
        tm1 = fmaxf(tm1, __shfl_xor_sync(0xffffffffu, tm1, 2));
        const float mn0 = fmaxf(m0, tm0), mn1 = fmaxf(m1, tm1);
        const float c0 = ex2f(m0 - mn0), c1 = ex2f(m1 - mn1);
        m0 = mn0; m1 = mn1;

        float rs0 = 0.0f, rs1 = 0.0f;
        uint32_t ap[4][4];
#pragma unroll
        for (int t = 0; t < 8; t++) {
            float p00 = ex2f(sacc[t][0] - m0);
            float p01 = ex2f(sacc[t][1] - m0);
            float p10 = ex2f(sacc[t][2] - m1);
            float p11 = ex2f(sacc[t][3] - m1);
            rs0 += p00 + p01; rs1 += p10 + p11;
            const int kc2 = t >> 1, hf = (t & 1) << 1;
            ap[kc2][hf] = pack_h2(p00, p01);
            ap[kc2][hf + 1] = pack_h2(p10, p11);
        }
        rs0 += __shfl_xor_sync(0xffffffffu, rs0, 1);
        rs0 += __shfl_xor_sync(0xffffffffu, rs0, 2);
        rs1 += __shfl_xor_sync(0xffffffffu, rs1, 1);
        rs1 += __shfl_xor_sync(0xffffffffu, rs1, 2);
        l0 = l0 * c0 + rs0;
        l1 = l1 * c1 + rs1;
#pragma unroll
        for (int t = 0; t < 8; t++) {
            oacc[t][0] *= c0; oacc[t][1] *= c0;
            oacc[t][2] *= c1; oacc[t][3] *= c1;
        }

        // O += Ph * Vh
#pragma unroll
        for (int kc2 = 0; kc2 < 4; kc2++) {
#pragma unroll
            for (int dnb = 0; dnb < 4; dnb++) {
                uint32_t vf[2][2];
                const uint32_t va = stg + 9216 +
                    ((kc2 << 4) + (lane & 15)) * 144 +
                    ((dnb << 4) + ((lane >> 4) << 3)) * 2;
                LDSM4T(vf[0], vf[1], va);
#pragma unroll
                for (int tt = 0; tt < 2; tt++)
                    mma16816(oacc[(dnb << 1) + tt], ap[kc2], vf[tt]);
            }
        }
        __syncthreads();
    }

    const float inv0 = 1.0f / l0, inv1 = 1.0f / l1;
#pragma unroll
    for (int t = 0; t < 8; t++) {
        const int d = (t << 3) + ((lane & 3) << 1);
        const size_t o0 = ((size_t)(b * Sn + qr0)) * Hn + h * 64 + d;
        const size_t o1 = ((size_t)(b * Sn + qr0 + 8)) * Hn + h * 64 + d;
        *(uint32_t*)(Ch + o0) = pack_h2(oacc[t][0] * inv0, oacc[t][1] * inv0);
        *(uint32_t*)(Ch + o1) = pack_h2(oacc[t][2] * inv1, oacc[t][3] * inv1);
    }
}

// ---------------------------------------------------------------------------
// LayerNorm over H=512: one WARP per row, 8 rows per 256-thread block.
// ---------------------------------------------------------------------------
__global__ void __launch_bounds__(256) ln_kernel(
    const float* __restrict__ in, const float* __restrict__ g,
    const float* __restrict__ bta, float* __restrict__ out,
    __half* __restrict__ ho)
{
    const int warp = threadIdx.x >> 5, lane = threadIdx.x & 31;
    const size_t base = ((size_t)blockIdx.x * 8 + warp) * Hn;
    float v[16];
    float s = 0.0f;
#pragma unroll
    for (int i = 0; i < 4; i++) {
        float4 t = *(const float4*)(in + base + (i << 7) + (lane << 2));
        v[i * 4 + 0] = t.x; v[i * 4 + 1] = t.y;
        v[i * 4 + 2] = t.z; v[i * 4 + 3] = t.w;
        s += t.x + t.y + t.z + t.w;
    }
#pragma unroll
    for (int o = 16; o; o >>= 1) s += __shfl_xor_sync(0xffffffffu, s, o);
    const float mean = s * (1.0f / Hn);
    float vv = 0.0f;
#pragma unroll
    for (int j = 0; j < 16; j++) {
        v[j] -= mean;
        vv = fmaf(v[j], v[j], vv);
    }
#pragma unroll
    for (int o = 16; o; o >>= 1) vv += __shfl_xor_sync(0xffffffffu, vv, o);
    const float inv = rsqrtf(vv * (1.0f / Hn) + 1e-12f);
#pragma unroll
    for (int i = 0; i < 4; i++) {
        const int col = (i << 7) + (lane << 2);
        float4 gv = *(const float4*)(g + col);
        float4 bv = *(const float4*)(bta + col);
        float y0 = v[i * 4 + 0] * inv * gv.x + bv.x;
        float y1 = v[i * 4 + 1] * inv * gv.y + bv.y;
        float y2 = v[i * 4 + 2] * inv * gv.z + bv.z;
        float y3 = v[i * 4 + 3] * inv * gv.w + bv.w;
        *(float4*)(out + base + col) = make_float4(y0, y1, y2, y3);
        if (ho) {
            uint2 p;
            p.x = pack_h2(y0, y1);
            p.y = pack_h2(y2, y3);
            *(uint2*)(ho + base + col) = p;
        }
    }
}

// ---------------------------------------------------------------------------
extern "C" void kernel_launch(void* const* d_in, const int* in_sizes, int n_in,
                              void* d_out, int out_size)
{
    (void)in_sizes; (void)n_in; (void)out_size;
    const float* qs   = (const float*)d_in[0];
    const float* mask = (const float*)d_in[1];
    const float* pb   = (const float*)d_in[2];
    const int*   ts   = (const int*)d_in[3];
    const float* wq  = (const float*)d_in[4];  const float* bq  = (const float*)d_in[5];
    const float* wk  = (const float*)d_in[6];  const float* bk  = (const float*)d_in[7];
    const float* wv  = (const float*)d_in[8];  const float* bv  = (const float*)d_in[9];
    const float* wo  = (const float*)d_in[10]; const float* bo  = (const float*)d_in[11];
    const float* l1g = (const float*)d_in[12]; const float* l1b = (const float*)d_in[13];
    const float* wi  = (const float*)d_in[14]; const float* bi  = (const float*)d_in[15];
    const float* wo2 = (const float*)d_in[16]; const float* bo2 = (const float*)d_in[17];
    const float* l2g = (const float*)d_in[18]; const float* l2b = (const float*)d_in[19];

    float *x, *attn, *bqkv;
    cudaGetSymbolAddress((void**)&x,    g_x);
    cudaGetSymbolAddress((void**)&attn, g_attn);
    cudaGetSymbolAddress((void**)&bqkv, g_bqkv);

    __half *qkv, *ch, *xh, *th, *fh;
    __half2 *auxp;
    cudaGetSymbolAddress((void**)&qkv, g_qkv);
    cudaGetSymbolAddress((void**)&ch, g_ch);
    cudaGetSymbolAddress((void**)&xh, g_xh);
    cudaGetSymbolAddress((void**)&th, g_th);
    cudaGetSymbolAddress((void**)&fh, g_fh);
    cudaGetSymbolAddress((void**)&auxp, g_aux);

    __half *wqkvp, *wop, *wip, *w2p;
    cudaGetSymbolAddress((void**)&wqkvp, g_wqkv);
    cudaGetSymbolAddress((void**)&wop, g_wo);
    cudaGetSymbolAddress((void**)&wip, g_wi);
    cudaGetSymbolAddress((void**)&w2p, g_w2);

    const int HM_SMEM = 2 * STAGE_BYTES;  // 37888
    const int FL_SMEM = 18432 + 2 * FSTG; // 55296
    cudaFuncSetAttribute(hmma_gemm<0>, cudaFuncAttributeMaxDynamicSharedMemorySize, HM_SMEM);
    cudaFuncSetAttribute(hmma_gemm<1>, cudaFuncAttributeMaxDynamicSharedMemorySize, HM_SMEM);
    cudaFuncSetAttribute(hmma_gemm<2>, cudaFuncAttributeMaxDynamicSharedMemorySize, HM_SMEM);
    cudaFuncSetAttribute(flash_kernel, cudaFuncAttributeMaxDynamicSharedMemorySize, FL_SMEM);

    prep_kernel<<<6147, 256>>>(wq, wk, wv, wo, wi, wo2, bq, bk, bv,
                               wqkvp, wop, wip, w2p, bqkv);
    aux_kernel<<<Bn * Sn, 256>>>(ts, pb, mask, auxp);
    cvt_h_kernel<<<(Mn * Hn) / 2048, 256>>>(qs, xh, Mn * Hn);

    dim3 gqkv(QKVS / 128, Mn / 128);  // (12, 64)
    dim3 gproj(Hn / 128, Mn / 128);   // (4, 64)
    dim3 gff(Fn / 128, Mn / 128);     // (16, 64)
    dim3 gfl(Sn / 128, Bn * NHn);     // (16, 32)

    for (int l = 0; l < Ln; l++) {
        const size_t wOff  = (size_t)l * Hn * Hn;
        const size_t bOff  = (size_t)l * Hn;
        const size_t wiOff = (size_t)l * Hn * Fn;
        const size_t biOff = (size_t)l * Fn;
        const float* xres = (l == 0) ? qs : x;

        hmma_gemm<0><<<gqkv, 256, HM_SMEM>>>(xh,
            wqkvp + (size_t)l * Hn * QKVS, bqkv + l * QKVS,
            nullptr, nullptr, qkv, Hn, QKVS);

        flash_kernel<<<gfl, 256, FL_SMEM>>>(qkv, auxp, ch);

        hmma_gemm<1><<<gproj, 256, HM_SMEM>>>(ch, wop + wOff, bo + bOff,
                                              xres, attn, nullptr, Hn, Hn);
        ln_kernel<<<Mn / 8, 256>>>(attn, l1g + bOff, l1b + bOff, attn, th);

        hmma_gemm<2><<<gff, 256, HM_SMEM>>>(th, wip + wiOff, bi + biOff,
                                            nullptr, nullptr, fh, Hn, Fn);
        hmma_gemm<1><<<gproj, 256, HM_SMEM>>>(fh, w2p + wiOff, bo2 + bOff,
                                              attn, x, nullptr, Fn, Hn);

        float* lnout = (l == Ln - 1) ? (float*)d_out : x;
        ln_kernel<<<Mn / 8, 256>>>(x, l2g + bOff, l2b + bOff, lnout,
                                   (l == Ln - 1) ? nullptr : xh);
    }
}